// round 2
// baseline (speedup 1.0000x reference)
#include <cuda_runtime.h>

#define NNODES 50000
#define NEDGES 800000
#define DF 128          // per-half feature dim (agg | x)
#define KTOT 256        // concatenated K

// ---------------- device scratch (no allocations allowed) ----------------
__device__ int   g_deg[NNODES];
__device__ int   g_fill[NNODES];
__device__ int   g_ptr[NNODES + 1];
__device__ int   g_csr[NEDGES];
__device__ float g_agg[(size_t)NNODES * DF];
__device__ float g_h[(size_t)NNODES * DF];
__device__ float g_B0[KTOT * 128];
__device__ float g_B1[KTOT * 128];
__device__ float g_B2[KTOT * 64];
__device__ float g_c0[128];
__device__ float g_c1[128];
__device__ float g_c2[64];

// ---------------- CSR build ----------------
__global__ void zero_kernel() {
    int i = blockIdx.x * blockDim.x + threadIdx.x;
    if (i < NNODES) { g_deg[i] = 0; g_fill[i] = 0; }
}

__global__ void hist_kernel(const int* __restrict__ dst) {
    int e = blockIdx.x * blockDim.x + threadIdx.x;
    if (e < NEDGES) atomicAdd(&g_deg[dst[e]], 1);
}

// single-block exclusive scan over g_deg -> g_ptr (N=50000, chunked)
__global__ void scan_kernel() {
    __shared__ int s[1024];
    int t = threadIdx.x;
    const int CH = (NNODES + 1023) / 1024;
    int start = t * CH;
    int end = min(start + CH, NNODES);
    int local = 0;
    for (int i = start; i < end; i++) local += g_deg[i];
    s[t] = local;
    __syncthreads();
    for (int off = 1; off < 1024; off <<= 1) {
        int v = (t >= off) ? s[t - off] : 0;
        __syncthreads();
        s[t] += v;
        __syncthreads();
    }
    int run = (t == 0) ? 0 : s[t - 1];
    for (int i = start; i < end; i++) { g_ptr[i] = run; run += g_deg[i]; }
    if (end == NNODES) g_ptr[NNODES] = run;
}

__global__ void fill_kernel(const int* __restrict__ src,
                            const int* __restrict__ dst) {
    int e = blockIdx.x * blockDim.x + threadIdx.x;
    if (e < NEDGES) {
        int d = dst[e];
        int pos = g_ptr[d] + atomicAdd(&g_fill[d], 1);
        g_csr[pos] = src[e];
    }
}

// ---------------- combined weights: Bcat = [Wl ; Wr+Ws], c = bl+bs ----------------
__global__ void combine_kernel(const float* __restrict__ Wl, const float* __restrict__ Wr,
                               const float* __restrict__ Ws, const float* __restrict__ bl,
                               const float* __restrict__ bs, float* __restrict__ Bc,
                               float* __restrict__ bc, int dout) {
    int i = blockIdx.x * blockDim.x + threadIdx.x;
    if (i < KTOT * dout) {
        int k = i / dout, n = i % dout;
        Bc[i] = (k < DF) ? Wl[k * dout + n]
                         : Wr[(k - DF) * dout + n] + Ws[(k - DF) * dout + n];
    }
    if (i < dout) bc[i] = bl[i] + bs[i];
}

// ---------------- mean aggregation: warp per node, lane = 4 cols ----------------
__global__ void agg_kernel(const float* __restrict__ X) {
    int warp = (blockIdx.x * blockDim.x + threadIdx.x) >> 5;
    int lane = threadIdx.x & 31;
    if (warp >= NNODES) return;
    int e0 = g_ptr[warp], e1 = g_ptr[warp + 1];
    const float4* __restrict__ X4 = (const float4*)X;
    float4 a0 = make_float4(0.f, 0.f, 0.f, 0.f);
    float4 a1 = make_float4(0.f, 0.f, 0.f, 0.f);
    float4 a2 = make_float4(0.f, 0.f, 0.f, 0.f);
    float4 a3 = make_float4(0.f, 0.f, 0.f, 0.f);
    int e = e0;
    for (; e + 3 < e1; e += 4) {
        int s0 = g_csr[e], s1 = g_csr[e + 1], s2 = g_csr[e + 2], s3 = g_csr[e + 3];
        float4 v0 = X4[s0 * 32 + lane];
        float4 v1 = X4[s1 * 32 + lane];
        float4 v2 = X4[s2 * 32 + lane];
        float4 v3 = X4[s3 * 32 + lane];
        a0.x += v0.x; a0.y += v0.y; a0.z += v0.z; a0.w += v0.w;
        a1.x += v1.x; a1.y += v1.y; a1.z += v1.z; a1.w += v1.w;
        a2.x += v2.x; a2.y += v2.y; a2.z += v2.z; a2.w += v2.w;
        a3.x += v3.x; a3.y += v3.y; a3.z += v3.z; a3.w += v3.w;
    }
    for (; e < e1; e++) {
        int s0 = g_csr[e];
        float4 v0 = X4[s0 * 32 + lane];
        a0.x += v0.x; a0.y += v0.y; a0.z += v0.z; a0.w += v0.w;
    }
    int cnt = e1 - e0;
    float sc = 1.0f / (float)max(cnt, 1);
    float4 r;
    r.x = (a0.x + a1.x + a2.x + a3.x) * sc;
    r.y = (a0.y + a1.y + a2.y + a3.y) * sc;
    r.z = (a0.z + a1.z + a2.z + a3.z) * sc;
    r.w = (a0.w + a1.w + a2.w + a3.w) * sc;
    ((float4*)g_agg)[warp * 32 + lane] = r;
}

// ---------------- fused SGEMM: C = [Aagg | Ax] @ Bcat + bias (opt. relu) ----------------
// K=256 fixed. BM=128, BK=16, 256 threads, 8xTN microtile, register-staged single buffer.
template <int BN, int TN, bool RELU>
__global__ void __launch_bounds__(256)
gemm_kernel(const float* __restrict__ Aagg, const float* __restrict__ Ax,
            const float* __restrict__ B, const float* __restrict__ bias,
            float* __restrict__ C, int M) {
    constexpr int BM = 128, BK = 16, TM = 8;
    constexpr int NCH = KTOT / BK;             // 16 chunks
    constexpr int A_F4 = BM * BK / 4 / 256;    // 2
    constexpr int B_F4 = BK * BN / 4 / 256;    // 2 (BN=128) or 1 (BN=64)
    __shared__ float As[BK][BM];
    __shared__ float Bs[BK][BN];

    int tid = threadIdx.x;
    int m0 = blockIdx.x * BM;
    constexpr int TX = BN / TN;                // 16
    int tx = tid % TX;
    int ty = tid / TX;                         // 0..15

    float acc[TM][TN];
#pragma unroll
    for (int i = 0; i < TM; i++)
#pragma unroll
        for (int j = 0; j < TN; j++) acc[i][j] = 0.f;

    float4 areg[A_F4], breg[B_F4];

    auto fetch = [&](int c) {
        int kc = c * BK;
#pragma unroll
        for (int l = 0; l < A_F4; l++) {
            int f = tid + l * 256;
            int row = f >> 2;                  // 0..127
            int k4 = (f & 3) * 4;              // 0,4,8,12
            int m = m0 + row;
            int kg = kc + k4;
            const float* Ap = (kg < DF) ? (Aagg + m * DF + kg)
                                        : (Ax + m * DF + (kg - DF));
            areg[l] = (m < M) ? *(const float4*)Ap : make_float4(0.f, 0.f, 0.f, 0.f);
        }
#pragma unroll
        for (int l = 0; l < B_F4; l++) {
            int f = tid + l * 256;
            int row = f / (BN / 4);
            int c4 = (f % (BN / 4)) * 4;
            breg[l] = *(const float4*)(B + (kc + row) * BN + c4);
        }
    };
    auto stage = [&]() {
#pragma unroll
        for (int l = 0; l < A_F4; l++) {
            int f = tid + l * 256;
            int row = f >> 2;
            int k4 = (f & 3) * 4;
            As[k4 + 0][row] = areg[l].x;
            As[k4 + 1][row] = areg[l].y;
            As[k4 + 2][row] = areg[l].z;
            As[k4 + 3][row] = areg[l].w;
        }
#pragma unroll
        for (int l = 0; l < B_F4; l++) {
            int f = tid + l * 256;
            int row = f / (BN / 4);
            int c4 = (f % (BN / 4)) * 4;
            *(float4*)&Bs[row][c4] = breg[l];
        }
    };

    fetch(0);
#pragma unroll
    for (int c = 0; c < NCH; c++) {
        stage();
        __syncthreads();
        if (c + 1 < NCH) fetch(c + 1);  // LDGs in flight under compute
#pragma unroll
        for (int kk = 0; kk < BK; kk++) {
            float ra[TM], rb[TN];
#pragma unroll
            for (int i = 0; i < TM; i += 4)
                *(float4*)&ra[i] = *(const float4*)&As[kk][ty * TM + i];
#pragma unroll
            for (int j = 0; j < TN; j += 4)
                *(float4*)&rb[j] = *(const float4*)&Bs[kk][tx * TN + j];
#pragma unroll
            for (int i = 0; i < TM; i++)
#pragma unroll
                for (int j = 0; j < TN; j++) acc[i][j] += ra[i] * rb[j];
        }
        __syncthreads();
    }

#pragma unroll
    for (int i = 0; i < TM; i++) {
        int m = m0 + ty * TM + i;
        if (m < M) {
#pragma unroll
            for (int j = 0; j < TN; j += 4) {
                float4 o;
                o.x = acc[i][j + 0] + bias[tx * TN + j + 0];
                o.y = acc[i][j + 1] + bias[tx * TN + j + 1];
                o.z = acc[i][j + 2] + bias[tx * TN + j + 2];
                o.w = acc[i][j + 3] + bias[tx * TN + j + 3];
                if (RELU) {
                    o.x = fmaxf(o.x, 0.f);
                    o.y = fmaxf(o.y, 0.f);
                    o.z = fmaxf(o.z, 0.f);
                    o.w = fmaxf(o.w, 0.f);
                }
                *(float4*)&C[m * BN + tx * TN + j] = o;
            }
        }
    }
}

// ---------------- launch ----------------
extern "C" void kernel_launch(void* const* d_in, const int* in_sizes, int n_in,
                              void* d_out, int out_size) {
    const float* x = (const float*)d_in[0];
    // JAX canonicalizes int64 -> int32 (x64 disabled), so edge_index is int32.
    const int* ei = (const int*)d_in[1];
    // d_in[2] edge_attr, d_in[3] edge_weight: unused by reference
    const float* Wl0 = (const float*)d_in[4];
    const float* bl0 = (const float*)d_in[5];
    const float* Wr0 = (const float*)d_in[6];
    const float* Ws0 = (const float*)d_in[7];
    const float* bs0 = (const float*)d_in[8];
    const float* Wl1 = (const float*)d_in[9];
    const float* bl1 = (const float*)d_in[10];
    const float* Wr1 = (const float*)d_in[11];
    const float* Ws1 = (const float*)d_in[12];
    const float* bs1 = (const float*)d_in[13];
    const float* Wl2 = (const float*)d_in[14];
    const float* bl2 = (const float*)d_in[15];
    const float* Wr2 = (const float*)d_in[16];
    const float* Ws2 = (const float*)d_in[17];
    const float* bs2 = (const float*)d_in[18];

    const int* src = ei;
    const int* dst = ei + NEDGES;

    float *agg, *h, *B0, *B1, *B2, *c0, *c1, *c2;
    cudaGetSymbolAddress((void**)&agg, g_agg);
    cudaGetSymbolAddress((void**)&h, g_h);
    cudaGetSymbolAddress((void**)&B0, g_B0);
    cudaGetSymbolAddress((void**)&B1, g_B1);
    cudaGetSymbolAddress((void**)&B2, g_B2);
    cudaGetSymbolAddress((void**)&c0, g_c0);
    cudaGetSymbolAddress((void**)&c1, g_c1);
    cudaGetSymbolAddress((void**)&c2, g_c2);

    // CSR build (shared by all 3 layers)
    zero_kernel<<<(NNODES + 255) / 256, 256>>>();
    hist_kernel<<<(NEDGES + 255) / 256, 256>>>(dst);
    scan_kernel<<<1, 1024>>>();
    fill_kernel<<<(NEDGES + 255) / 256, 256>>>(src, dst);

    // weight fusion: Bcat = [Wl ; Wr+Ws], bias = bl+bs
    combine_kernel<<<(KTOT * 128 + 255) / 256, 256>>>(Wl0, Wr0, Ws0, bl0, bs0, B0, c0, 128);
    combine_kernel<<<(KTOT * 128 + 255) / 256, 256>>>(Wl1, Wr1, Ws1, bl1, bs1, B1, c1, 128);
    combine_kernel<<<(KTOT * 64 + 255) / 256, 256>>>(Wl2, Wr2, Ws2, bl2, bs2, B2, c2, 64);

    int aggGrid = (NNODES * 32 + 255) / 256;   // warp per node, 8 warps/block
    int gemmGrid = (NNODES + 127) / 128;

    // layer 0: h = relu([agg(x) | x] @ B0 + c0)
    agg_kernel<<<aggGrid, 256>>>(x);
    gemm_kernel<128, 8, true><<<gemmGrid, 256>>>(agg, x, B0, c0, h, NNODES);
    // layer 1: h = relu([agg(h) | h] @ B1 + c1)   (in-place h is tile-safe)
    agg_kernel<<<aggGrid, 256>>>(h);
    gemm_kernel<128, 8, true><<<gemmGrid, 256>>>(agg, h, B1, c1, h, NNODES);
    // layer 2: out = [agg(h) | h] @ B2 + c2
    agg_kernel<<<aggGrid, 256>>>(h);
    gemm_kernel<64, 4, false><<<gemmGrid, 256>>>(agg, h, B2, c2, (float*)d_out, NNODES);
}